// round 3
// baseline (speedup 1.0000x reference)
#include <cuda_runtime.h>
#include <math.h>
#include <cstdint>

#define TT 1024
#define BB 4
#define CC 1024
#define EE 8
#define HH 16
#define DD 64
#define NT 4096   // B*T tokens
#define NR 8192   // 2 slots * NT rows

// ---------------- scratch (device globals; no allocs allowed) ----------------
__device__ float g_k [(size_t)NT * CC];
__device__ float g_v [(size_t)NT * CC];
__device__ float g_q [(size_t)NR * CC];
__device__ float g_at[(size_t)NR * CC];
__device__ float g_o [(size_t)NR * CC];
__device__ float g_w [NR];            // routing weight per encoded row r = s*NT + token
__device__ int   g_rl[EE][NT];        // per-expert encoded row list
__device__ int   g_cnt[EE];

__global__ void zero_cnt() { if (threadIdx.x < EE) g_cnt[threadIdx.x] = 0; }

// ---------------- gating: logits + top2 + softmax + scatter ----------------
__global__ __launch_bounds__(256) void gate_kernel(
    const float* __restrict__ x, const float* __restrict__ noise,
    const float* __restrict__ Wg, const float* __restrict__ Wn)
{
    int row = blockIdx.x;           // token
    int tid = threadIdx.x;
    const float* xr = x + (size_t)row * CC;

    float accg[8], accn[8];
#pragma unroll
    for (int e = 0; e < 8; e++) { accg[e] = 0.f; accn[e] = 0.f; }

    for (int c = tid; c < CC; c += 256) {
        float xv = xr[c];
        const float* wg = Wg + c * 8;
        const float* wn = Wn + c * 8;
#pragma unroll
        for (int e = 0; e < 8; e++) { accg[e] += xv * wg[e]; accn[e] += xv * wn[e]; }
    }

    __shared__ float red[16][256];
#pragma unroll
    for (int e = 0; e < 8; e++) { red[e][tid] = accg[e]; red[8 + e][tid] = accn[e]; }
    __syncthreads();

    __shared__ float fin[16];
    if (tid < 16) {
        float s = 0.f;
        for (int i = 0; i < 256; i++) s += red[tid][i];
        fin[tid] = s;
    }
    __syncthreads();

    if (tid == 0) {
        float logit[8];
#pragma unroll
        for (int e = 0; e < 8; e++) {
            float z  = fin[8 + e];
            float sp = (z > 20.f) ? z : log1pf(expf(z));   // softplus
            logit[e] = fin[e] + noise[row * 8 + e] * sp;
        }
        // top-2 (first occurrence wins ties, matching lax.top_k)
        int i0 = 0; float v0 = logit[0];
#pragma unroll
        for (int e = 1; e < 8; e++) if (logit[e] > v0) { v0 = logit[e]; i0 = e; }
        int i1 = -1; float v1 = -INFINITY;
#pragma unroll
        for (int e = 0; e < 8; e++) if (e != i0 && logit[e] > v1) { v1 = logit[e]; i1 = e; }
        // softmax over [v0, v1]
        float p1 = 1.f / (1.f + expf(v0 - v1));
        float p0 = 1.f - p1;
        g_w[row]      = p0;
        g_w[NT + row] = p1;
        int pos0 = atomicAdd(&g_cnt[i0], 1); g_rl[i0][pos0] = row;        // slot 0: r = token
        int pos1 = atomicAdd(&g_cnt[i1], 1); g_rl[i1][pos1] = NT + row;   // slot 1: r = NT + token
    }
}

// ---------------- dense fp32 GEMM: C[M,N] = A[M,K] @ B[K,N]; 128x128x8 tiles ----------------
__global__ __launch_bounds__(256) void gemm_dense(
    const float* __restrict__ A, const float* __restrict__ Bm, float* __restrict__ C)
{
    const int N = CC, K = CC;
    __shared__ float As[8][128];
    __shared__ float Bs[8][128];
    int tid = threadIdx.x;
    const float* Ab = A  + (size_t)blockIdx.y * 128 * K;
    const float* Bb = Bm + (size_t)blockIdx.x * 128;
    float* Cb = C + (size_t)blockIdx.y * 128 * N + (size_t)blockIdx.x * 128;

    int arow = tid >> 1, acol = (tid & 1) * 4;
    int brow = tid >> 5, bcol = (tid & 31) * 4;
    int tx = tid & 15, ty = tid >> 4;

    float acc[8][8];
#pragma unroll
    for (int i = 0; i < 8; i++)
#pragma unroll
        for (int j = 0; j < 8; j++) acc[i][j] = 0.f;

    for (int k0 = 0; k0 < K; k0 += 8) {
        float4 a4 = *(const float4*)(Ab + (size_t)arow * K + k0 + acol);
        float4 b4 = *(const float4*)(Bb + (size_t)(k0 + brow) * N + bcol);
        As[acol + 0][arow] = a4.x; As[acol + 1][arow] = a4.y;
        As[acol + 2][arow] = a4.z; As[acol + 3][arow] = a4.w;
        *(float4*)&Bs[brow][bcol] = b4;
        __syncthreads();
#pragma unroll
        for (int kk = 0; kk < 8; kk++) {
            float ra[8], rb[8];
#pragma unroll
            for (int i = 0; i < 8; i++) ra[i] = As[kk][ty * 8 + i];
#pragma unroll
            for (int j = 0; j < 8; j++) rb[j] = Bs[kk][tx * 8 + j];
#pragma unroll
            for (int i = 0; i < 8; i++)
#pragma unroll
                for (int j = 0; j < 8; j++) acc[i][j] += ra[i] * rb[j];
        }
        __syncthreads();
    }
#pragma unroll
    for (int i = 0; i < 8; i++)
#pragma unroll
        for (int j = 0; j < 8; j += 4)
            *(float4*)(Cb + (size_t)(ty * 8 + i) * N + tx * 8 + j) =
                make_float4(acc[i][j], acc[i][j + 1], acc[i][j + 2], acc[i][j + 3]);
}

// ---------------- grouped (expert-gathered) GEMM ----------------
// For expert e: rows come from g_rl[e][...]; source row = token (r & (NT-1)) if token_mode
// else the encoded row r itself; B = Bbase + e*CC*CC; output row = r in Cdst.
__global__ __launch_bounds__(256) void gemm_group(
    const float* __restrict__ Asrc, const float* __restrict__ Bbase,
    float* __restrict__ Cdst, int token_mode)
{
    const int N = CC, K = CC;
    int e = blockIdx.z;
    int cnt = g_cnt[e];
    int row0 = blockIdx.y * 128;
    if (row0 >= cnt) return;

    __shared__ float As[8][128];
    __shared__ float Bs[8][128];
    int tid = threadIdx.x;
    const float* Bb = Bbase + (size_t)e * CC * CC + (size_t)blockIdx.x * 128;

    int arow = tid >> 1, acol = (tid & 1) * 4;
    int brow = tid >> 5, bcol = (tid & 31) * 4;
    int tx = tid & 15, ty = tid >> 4;

    int gr = row0 + arow;
    bool avalid = (gr < cnt);
    int srcrow = 0;
    if (avalid) {
        int r = g_rl[e][gr];
        srcrow = token_mode ? (r & (NT - 1)) : r;
    }

    float acc[8][8];
#pragma unroll
    for (int i = 0; i < 8; i++)
#pragma unroll
        for (int j = 0; j < 8; j++) acc[i][j] = 0.f;

    for (int k0 = 0; k0 < K; k0 += 8) {
        float4 a4 = make_float4(0.f, 0.f, 0.f, 0.f);
        if (avalid) a4 = *(const float4*)(Asrc + (size_t)srcrow * K + k0 + acol);
        float4 b4 = *(const float4*)(Bb + (size_t)(k0 + brow) * N + bcol);
        As[acol + 0][arow] = a4.x; As[acol + 1][arow] = a4.y;
        As[acol + 2][arow] = a4.z; As[acol + 3][arow] = a4.w;
        *(float4*)&Bs[brow][bcol] = b4;
        __syncthreads();
#pragma unroll
        for (int kk = 0; kk < 8; kk++) {
            float ra[8], rb[8];
#pragma unroll
            for (int i = 0; i < 8; i++) ra[i] = As[kk][ty * 8 + i];
#pragma unroll
            for (int j = 0; j < 8; j++) rb[j] = Bs[kk][tx * 8 + j];
#pragma unroll
            for (int i = 0; i < 8; i++)
#pragma unroll
                for (int j = 0; j < 8; j++) acc[i][j] += ra[i] * rb[j];
        }
        __syncthreads();
    }
#pragma unroll
    for (int i = 0; i < 8; i++) {
        int gro = row0 + ty * 8 + i;
        if (gro < cnt) {
            int rr = g_rl[e][gro];
            float* crow = Cdst + (size_t)rr * N + (size_t)blockIdx.x * 128 + tx * 8;
#pragma unroll
            for (int j = 0; j < 8; j += 4)
                *(float4*)(crow + j) =
                    make_float4(acc[i][j], acc[i][j + 1], acc[i][j + 2], acc[i][j + 3]);
        }
    }
}

// ---------------- causal attention per (slot, b, h), 8 query rows / block ----------------
__global__ __launch_bounds__(256) void attn_kernel()
{
    int bx = blockIdx.x;                // query row tile (8 rows)
    int h  = blockIdx.y;
    int zb = blockIdx.z;                // s*4 + b
    int s  = zb >> 2;
    int b  = zb & 3;

    __shared__ float Q[8][64];
    __shared__ float S[8][1024];
    __shared__ float KV[32 * 65];       // padded: row stride 65

    int tid  = threadIdx.x;
    int w    = tid >> 5;
    int lane = tid & 31;

    int t0 = bx * 8;
    int rbase = s * NT + b * TT;        // encoded-row base for this (slot, batch)

    // load 8 query rows
    for (int i = tid; i < 8 * 64; i += 256) {
        int rr = i >> 6, d = i & 63;
        Q[rr][d] = g_q[(size_t)(rbase + t0 + rr) * CC + h * 64 + d];
    }
    __syncthreads();

    int t      = t0 + w;
    int tmax   = t0 + 7;
    int ntiles = tmax / 32 + 1;
    const float scale = 0.125f;         // 1/sqrt(64)
    size_t kvbase = (size_t)(b * TT) * CC + h * 64;

    // phase A: scores into smem
    for (int kt = 0; kt < ntiles; kt++) {
        int j0 = kt * 32;
        for (int i = tid; i < 32 * 64; i += 256) {
            int jj = i >> 6, d = i & 63;
            KV[jj * 65 + d] = g_k[kvbase + (size_t)(j0 + jj) * CC + d];
        }
        __syncthreads();
        int j = j0 + lane;
        float sc;
        if (j <= t) {
            sc = 0.f;
#pragma unroll
            for (int d = 0; d < 64; d++) sc += Q[w][d] * KV[lane * 65 + d];
            sc *= scale;
        } else sc = -INFINITY;
        S[w][j] = sc;
        __syncthreads();
    }

    // phase B: row softmax (two-pass), overwrite S with unnormalized p
    int jmax = ntiles * 32;
    float m = -INFINITY;
    for (int j = lane; j < jmax; j += 32) m = fmaxf(m, S[w][j]);
#pragma unroll
    for (int o = 16; o; o >>= 1) m = fmaxf(m, __shfl_xor_sync(0xFFFFFFFFu, m, o));
    float l = 0.f;
    for (int j = lane; j < jmax; j += 32) {
        float p = expf(S[w][j] - m);
        S[w][j] = p;
        l += p;
    }
#pragma unroll
    for (int o = 16; o; o >>= 1) l += __shfl_xor_sync(0xFFFFFFFFu, l, o);

    // phase C: o = p @ V
    float o0 = 0.f, o1 = 0.f;
    for (int kt = 0; kt < ntiles; kt++) {
        __syncthreads();
        int j0 = kt * 32;
        for (int i = tid; i < 32 * 64; i += 256) {
            int jj = i >> 6, d = i & 63;
            KV[jj * 65 + d] = g_v[kvbase + (size_t)(j0 + jj) * CC + d];
        }
        __syncthreads();
#pragma unroll
        for (int jj = 0; jj < 32; jj++) {
            int j = j0 + jj;
            float p = (j <= t) ? S[w][j] : 0.f;
            o0 += p * KV[jj * 65 + lane];
            o1 += p * KV[jj * 65 + lane + 32];
        }
    }
    float inv = 1.f / l;
    size_t orow = (size_t)(rbase + t) * CC + h * 64;
    g_at[orow + lane]      = o0 * inv;
    g_at[orow + lane + 32] = o1 * inv;
}

// ---------------- final combine: out = w0*o(slot0) + w1*o(slot1) ----------------
__global__ void combine(float* __restrict__ out)
{
    int i = blockIdx.x * 256 + threadIdx.x;       // 0 .. NT*CC-1
    int token = i >> 10;
    out[i] = g_w[token] * g_o[i] + g_w[NT + token] * g_o[(size_t)NT * CC + i];
}

// ---------------- launch ----------------
extern "C" void kernel_launch(void* const* d_in, const int* in_sizes, int n_in,
                              void* d_out, int out_size)
{
    const float* x     = (const float*)d_in[0];
    const float* noise = (const float*)d_in[1];
    const float* Wk    = (const float*)d_in[2];
    const float* Wv    = (const float*)d_in[3];
    const float* Wq    = (const float*)d_in[4];
    const float* Wo    = (const float*)d_in[5];
    const float* Wg    = (const float*)d_in[6];
    const float* Wn    = (const float*)d_in[7];
    float* out = (float*)d_out;

    float *pk, *pv, *pq, *pat, *po;
    cudaGetSymbolAddress((void**)&pk,  g_k);
    cudaGetSymbolAddress((void**)&pv,  g_v);
    cudaGetSymbolAddress((void**)&pq,  g_q);
    cudaGetSymbolAddress((void**)&pat, g_at);
    cudaGetSymbolAddress((void**)&po,  g_o);

    zero_cnt<<<1, 32>>>();
    gate_kernel<<<NT, 256>>>(x, noise, Wg, Wn);

    gemm_dense<<<dim3(8, 32), 256>>>(x, Wk, pk);               // k = x @ Wk
    gemm_dense<<<dim3(8, 32), 256>>>(x, Wv, pv);               // v = x @ Wv

    gemm_group<<<dim3(8, 32, 8), 256>>>(x, Wq, pq, 1);         // q_sel = x @ Wq[sel]

    attn_kernel<<<dim3(TT / 8, HH, 8), 256>>>();               // causal attention per slot

    gemm_group<<<dim3(8, 32, 8), 256>>>(pat, Wo, po, 0);       // o_sel = attn @ Wo[sel]

    combine<<<(NT * CC) / 256, 256>>>(out);                    // weighted sum of slots
}

// round 5
// speedup vs baseline: 2.3110x; 2.3110x over previous
#include <cuda_runtime.h>
#include <math.h>
#include <cstdint>

#define TT 1024
#define CC 1024
#define EE 8
#define NT 4096   // B*T tokens
#define NR 8192   // 2 slots * NT rows

// ---------------- scratch (device globals; no allocs allowed) ----------------
__device__ float g_k [(size_t)NT * CC];
__device__ float g_v [(size_t)NT * CC];
__device__ float g_q [(size_t)NR * CC];
__device__ float g_at[(size_t)NR * CC];
__device__ float g_o [(size_t)NR * CC];
__device__ float g_w [NR];
__device__ int   g_rl[EE][NT];
__device__ int   g_cnt[EE];
// transposed weights (K-contiguous per output column)
__device__ float g_wkT[(size_t)CC * CC];
__device__ float g_wvT[(size_t)CC * CC];
__device__ float g_wqT[(size_t)EE * CC * CC];
__device__ float g_woT[(size_t)EE * CC * CC];

__global__ void zero_cnt() { if (threadIdx.x < EE) g_cnt[threadIdx.x] = 0; }

__device__ __forceinline__ uint32_t f2tf32(float x) {
    uint32_t u;
    asm("cvt.rna.tf32.f32 %0, %1;" : "=r"(u) : "f"(x));
    return u;
}
__device__ __forceinline__ void mma_tf32(float* d, const uint32_t* a, const uint32_t* b) {
    asm volatile(
        "mma.sync.aligned.m16n8k8.row.col.f32.tf32.tf32.f32 "
        "{%0,%1,%2,%3},{%4,%5,%6,%7},{%8,%9},{%0,%1,%2,%3};"
        : "+f"(d[0]), "+f"(d[1]), "+f"(d[2]), "+f"(d[3])
        : "r"(a[0]), "r"(a[1]), "r"(a[2]), "r"(a[3]), "r"(b[0]), "r"(b[1]));
}

// ---------------- gating ----------------
__global__ __launch_bounds__(256) void gate_kernel(
    const float* __restrict__ x, const float* __restrict__ noise,
    const float* __restrict__ Wg, const float* __restrict__ Wn)
{
    int row = blockIdx.x;
    int tid = threadIdx.x;
    const float* xr = x + (size_t)row * CC;

    float accg[8], accn[8];
#pragma unroll
    for (int e = 0; e < 8; e++) { accg[e] = 0.f; accn[e] = 0.f; }
    for (int c = tid; c < CC; c += 256) {
        float xv = xr[c];
        const float* wg = Wg + c * 8;
        const float* wn = Wn + c * 8;
#pragma unroll
        for (int e = 0; e < 8; e++) { accg[e] += xv * wg[e]; accn[e] += xv * wn[e]; }
    }
    __shared__ float red[16][256];
#pragma unroll
    for (int e = 0; e < 8; e++) { red[e][tid] = accg[e]; red[8 + e][tid] = accn[e]; }
    __syncthreads();
    __shared__ float fin[16];
    if (tid < 16) {
        float s = 0.f;
        for (int i = 0; i < 256; i++) s += red[tid][i];
        fin[tid] = s;
    }
    __syncthreads();
    if (tid == 0) {
        float logit[8];
#pragma unroll
        for (int e = 0; e < 8; e++) {
            float z  = fin[8 + e];
            float sp = (z > 20.f) ? z : log1pf(expf(z));
            logit[e] = fin[e] + noise[row * 8 + e] * sp;
        }
        int i0 = 0; float v0 = logit[0];
#pragma unroll
        for (int e = 1; e < 8; e++) if (logit[e] > v0) { v0 = logit[e]; i0 = e; }
        int i1 = -1; float v1 = -INFINITY;
#pragma unroll
        for (int e = 0; e < 8; e++) if (e != i0 && logit[e] > v1) { v1 = logit[e]; i1 = e; }
        float p1 = 1.f / (1.f + expf(v0 - v1));
        float p0 = 1.f - p1;
        g_w[row]      = p0;
        g_w[NT + row] = p1;
        int pos0 = atomicAdd(&g_cnt[i0], 1); g_rl[i0][pos0] = row;
        int pos1 = atomicAdd(&g_cnt[i1], 1); g_rl[i1][pos1] = NT + row;
    }
}

// ---------------- weight transpose (1024x1024 per z) ----------------
__global__ __launch_bounds__(256) void transpose_k(
    const float* __restrict__ W, float* __restrict__ Wt)
{
    __shared__ float t[32][33];
    int bx = blockIdx.x, by = blockIdx.y, z = blockIdx.z;
    const float* Wz = W + (size_t)z * CC * CC;
    float* Wtz = Wt + (size_t)z * CC * CC;
    int tx = threadIdx.x & 31, ty = threadIdx.x >> 5;
#pragma unroll
    for (int rr = 0; rr < 4; rr++)
        t[ty + rr * 8][tx] = Wz[(size_t)(by * 32 + ty + rr * 8) * CC + bx * 32 + tx];
    __syncthreads();
#pragma unroll
    for (int rr = 0; rr < 4; rr++)
        Wtz[(size_t)(bx * 32 + ty + rr * 8) * CC + by * 32 + tx] = t[tx][ty + rr * 8];
}

// ---------------- tf32 mma.sync GEMM: C[rows,1024] = A[rows,1024] @ Bt^T ----------------
// Bt is [n][k] K-contiguous. mode 0: dense (grid.z=1). mode 1: gather token rows
// (src = rl & 4095). mode 2: gather direct rows (src = rl).
// CTA: 128x128 tile, 256 threads = 8 warps (2x4), warp tile 64x32, K chunk 32.
#define SA 36   // smem row stride (words)
__global__ __launch_bounds__(256) void gemm_mma(
    const float* __restrict__ A, const float* __restrict__ Bt,
    float* __restrict__ C, int mode)
{
    __shared__ uint32_t As[2][128 * SA];
    __shared__ uint32_t Bs[2][128 * SA];
    __shared__ int s_src[128];
    __shared__ int s_dst[128];

    int tid  = threadIdx.x;
    int wid  = tid >> 5, lane = tid & 31;
    int e    = blockIdx.z;
    int row0 = blockIdx.y * 128;
    int n0   = blockIdx.x * 128;

    int cnt = NT;
    if (mode != 0) {
        cnt = g_cnt[e];
        if (row0 >= cnt) return;
    }
    if (tid < 128) {
        int gr = row0 + tid;
        if (mode == 0) { s_src[tid] = gr; s_dst[tid] = gr; }
        else if (gr < cnt) {
            int r = g_rl[e][gr];
            s_src[tid] = (mode == 1) ? (r & (NT - 1)) : r;
            s_dst[tid] = r;
        } else { s_src[tid] = 0; s_dst[tid] = -1; }
    }
    __syncthreads();

    const float* Brow = Bt + (size_t)e * CC * CC;
    int ldrow = tid >> 1;               // 0..127
    int ldcol = (tid & 1) * 16;         // 0 or 16
    const float* aptr = A + (size_t)s_src[ldrow] * CC + ldcol;
    const float* bptr = Brow + (size_t)(n0 + ldrow) * CC + ldcol;

    int wm = (wid >> 2) * 64;           // warp m offset
    int wn = (wid & 3) * 32;            // warp n offset

    float acc[4][4][4];
#pragma unroll
    for (int mt = 0; mt < 4; mt++)
#pragma unroll
        for (int nt = 0; nt < 4; nt++)
#pragma unroll
            for (int q = 0; q < 4; q++) acc[mt][nt][q] = 0.f;

    // prefetch chunk 0 into regs
    float ra[4][4], rb[4][4];
#pragma unroll
    for (int q = 0; q < 4; q++) {
        float4 va = *(const float4*)(aptr + q * 4);
        float4 vb = *(const float4*)(bptr + q * 4);
        ra[q][0] = va.x; ra[q][1] = va.y; ra[q][2] = va.z; ra[q][3] = va.w;
        rb[q][0] = vb.x; rb[q][1] = vb.y; rb[q][2] = vb.z; rb[q][3] = vb.w;
    }
    // store chunk 0
#pragma unroll
    for (int q = 0; q < 4; q++) {
        uint32_t* as = &As[0][ldrow * SA + ldcol + q * 4];
        uint32_t* bs = &Bs[0][ldrow * SA + ldcol + q * 4];
#pragma unroll
        for (int j = 0; j < 4; j++) { as[j] = f2tf32(ra[q][j]); bs[j] = f2tf32(rb[q][j]); }
    }
    __syncthreads();

#pragma unroll 1
    for (int c = 0; c < 32; c++) {
        int cur = c & 1;
        // prefetch next chunk (global -> regs)
        if (c + 1 < 32) {
            const float* ap = aptr + (c + 1) * 32;
            const float* bp = bptr + (c + 1) * 32;
#pragma unroll
            for (int q = 0; q < 4; q++) {
                float4 va = *(const float4*)(ap + q * 4);
                float4 vb = *(const float4*)(bp + q * 4);
                ra[q][0] = va.x; ra[q][1] = va.y; ra[q][2] = va.z; ra[q][3] = va.w;
                rb[q][0] = vb.x; rb[q][1] = vb.y; rb[q][2] = vb.z; rb[q][3] = vb.w;
            }
        }
        // compute on current buffer: 4 k8-steps
        const uint32_t* Ab = As[cur];
        const uint32_t* Bb = Bs[cur];
#pragma unroll
        for (int k8 = 0; k8 < 4; k8++) {
            int kc = k8 * 8 + (lane & 3);
            uint32_t af[4][4], bf[4][2];
#pragma unroll
            for (int mt = 0; mt < 4; mt++) {
                int r = wm + mt * 16 + (lane >> 2);
                af[mt][0] = Ab[r * SA + kc];
                af[mt][1] = Ab[(r + 8) * SA + kc];
                af[mt][2] = Ab[r * SA + kc + 4];
                af[mt][3] = Ab[(r + 8) * SA + kc + 4];
            }
#pragma unroll
            for (int nt = 0; nt < 4; nt++) {
                int n = wn + nt * 8 + (lane >> 2);
                bf[nt][0] = Bb[n * SA + kc];
                bf[nt][1] = Bb[n * SA + kc + 4];
            }
#pragma unroll
            for (int mt = 0; mt < 4; mt++)
#pragma unroll
                for (int nt = 0; nt < 4; nt++)
                    mma_tf32(acc[mt][nt], af[mt], bf[nt]);
        }
        // store next chunk (regs -> other buffer), then barrier
        if (c + 1 < 32) {
            int nxt = cur ^ 1;
#pragma unroll
            for (int q = 0; q < 4; q++) {
                uint32_t* as = &As[nxt][ldrow * SA + ldcol + q * 4];
                uint32_t* bs = &Bs[nxt][ldrow * SA + ldcol + q * 4];
#pragma unroll
                for (int j = 0; j < 4; j++) { as[j] = f2tf32(ra[q][j]); bs[j] = f2tf32(rb[q][j]); }
            }
            __syncthreads();
        }
    }

    // epilogue: d0/d1 at (r, c), d2/d3 at (r+8, c); c = 2*(lane&3)
    int r0 = wm + (lane >> 2);
    int cbase = n0 + wn + (lane & 3) * 2;
#pragma unroll
    for (int mt = 0; mt < 4; mt++) {
        int rA = r0 + mt * 16;
        int dA = s_dst[rA];
        int dB = s_dst[rA + 8];
#pragma unroll
        for (int nt = 0; nt < 4; nt++) {
            int gc = cbase + nt * 8;
            if (dA >= 0)
                *(float2*)(C + (size_t)dA * CC + gc) = make_float2(acc[mt][nt][0], acc[mt][nt][1]);
            if (dB >= 0)
                *(float2*)(C + (size_t)dB * CC + gc) = make_float2(acc[mt][nt][2], acc[mt][nt][3]);
        }
    }
}

// ---------------- flash attention: 64-row Q tiles, SIMT fp32 ----------------
// grid (16 qtiles, 16 heads, 8 = slot*4+b), 256 threads = 16x16, 4x4 per thread
#define APAD 68
__global__ __launch_bounds__(256) void attn_flash()
{
    extern __shared__ float sm[];
    float* Qt = sm;                  // [64][68] d-major (Q transposed)
    float* Kt = sm + 64 * APAD;      // [64][68] d-major (K transposed)
    float* Vs = sm + 2 * 64 * APAD;  // [64][68] j-major
    float* Pt = sm + 3 * 64 * APAD;  // [64][68] j-major (P transposed)

    int tid = threadIdx.x;
    int tx = tid & 15, ty = tid >> 4;
    int qt = blockIdx.x;
    int h  = blockIdx.y;
    int zb = blockIdx.z;
    int s = zb >> 2, b = zb & 3;
    int rbase = s * NT + b * TT;
    size_t qbase  = (size_t)(rbase + qt * 64) * CC + h * 64;
    size_t kvbase = (size_t)(b * TT) * CC + h * 64;

#pragma unroll
    for (int it = 0; it < 4; it++) {
        int i = tid + it * 256;
        int r = i >> 4, d0 = (i & 15) * 4;
        float4 v = *(const float4*)(g_q + qbase + (size_t)r * CC + d0);
        Qt[(d0 + 0) * APAD + r] = v.x; Qt[(d0 + 1) * APAD + r] = v.y;
        Qt[(d0 + 2) * APAD + r] = v.z; Qt[(d0 + 3) * APAD + r] = v.w;
    }

    float O[4][4];
    float mrow[4], lrow[4];
#pragma unroll
    for (int i = 0; i < 4; i++) {
        mrow[i] = -INFINITY; lrow[i] = 0.f;
#pragma unroll
        for (int j = 0; j < 4; j++) O[i][j] = 0.f;
    }
    const float scale = 0.125f;

    for (int kt = 0; kt <= qt; kt++) {
        __syncthreads();
        size_t kb = kvbase + (size_t)(kt * 64) * CC;
#pragma unroll
        for (int it = 0; it < 4; it++) {
            int i = tid + it * 256;
            int j = i >> 4, d0 = (i & 15) * 4;
            float4 kv = *(const float4*)(g_k + kb + (size_t)j * CC + d0);
            Kt[(d0 + 0) * APAD + j] = kv.x; Kt[(d0 + 1) * APAD + j] = kv.y;
            Kt[(d0 + 2) * APAD + j] = kv.z; Kt[(d0 + 3) * APAD + j] = kv.w;
            float4 vv = *(const float4*)(g_v + kb + (size_t)j * CC + d0);
            *(float4*)(Vs + j * APAD + d0) = vv;
        }
        __syncthreads();

        float S[4][4];
#pragma unroll
        for (int i = 0; i < 4; i++)
#pragma unroll
            for (int j = 0; j < 4; j++) S[i][j] = 0.f;
#pragma unroll 8
        for (int d = 0; d < 64; d++) {
            float4 rq = *(const float4*)(Qt + d * APAD + ty * 4);
            float4 rk = *(const float4*)(Kt + d * APAD + tx * 4);
            float a[4] = {rq.x, rq.y, rq.z, rq.w};
            float bb[4] = {rk.x, rk.y, rk.z, rk.w};
#pragma unroll
            for (int i = 0; i < 4; i++)
#pragma unroll
                for (int j = 0; j < 4; j++) S[i][j] += a[i] * bb[j];
        }
#pragma unroll
        for (int i = 0; i < 4; i++)
#pragma unroll
            for (int j = 0; j < 4; j++) {
                S[i][j] *= scale;
                if (kt == qt && (tx * 4 + j) > (ty * 4 + i)) S[i][j] = -INFINITY;
            }
#pragma unroll
        for (int i = 0; i < 4; i++) {
            float rm = fmaxf(fmaxf(S[i][0], S[i][1]), fmaxf(S[i][2], S[i][3]));
#pragma unroll
            for (int o = 1; o <= 8; o <<= 1) rm = fmaxf(rm, __shfl_xor_sync(0xFFFFFFFFu, rm, o));
            float mn = fmaxf(mrow[i], rm);
            float alpha = __expf(mrow[i] - mn);
            mrow[i] = mn;
            float rs = 0.f;
#pragma unroll
            for (int j = 0; j < 4; j++) {
                float p = __expf(S[i][j] - mn);
                S[i][j] = p;
                rs += p;
            }
#pragma unroll
            for (int o = 1; o <= 8; o <<= 1) rs += __shfl_xor_sync(0xFFFFFFFFu, rs, o);
            lrow[i] = lrow[i] * alpha + rs;
#pragma unroll
            for (int j = 0; j < 4; j++) O[i][j] *= alpha;
        }
#pragma unroll
        for (int j = 0; j < 4; j++)
#pragma unroll
            for (int i = 0; i < 4; i++)
                Pt[(tx * 4 + j) * APAD + ty * 4 + i] = S[i][j];
        __syncthreads();
#pragma unroll 8
        for (int j = 0; j < 64; j++) {
            float4 pa = *(const float4*)(Pt + j * APAD + ty * 4);
            float4 pb = *(const float4*)(Vs + j * APAD + tx * 4);
            float a[4] = {pa.x, pa.y, pa.z, pa.w};
            float bb[4] = {pb.x, pb.y, pb.z, pb.w};
#pragma unroll
            for (int i = 0; i < 4; i++)
#pragma unroll
                for (int jj = 0; jj < 4; jj++) O[i][jj] += a[i] * bb[jj];
        }
    }
#pragma unroll
    for (int i = 0; i < 4; i++) {
        float inv = 1.f / lrow[i];
        float* orow = g_at + (size_t)(rbase + qt * 64 + ty * 4 + i) * CC + h * 64 + tx * 4;
        *(float4*)orow = make_float4(O[i][0] * inv, O[i][1] * inv, O[i][2] * inv, O[i][3] * inv);
    }
}

// ---------------- final combine ----------------
__global__ void combine(float* __restrict__ out)
{
    int i = blockIdx.x * 256 + threadIdx.x;
    int token = i >> 10;
    out[i] = g_w[token] * g_o[i] + g_w[NT + token] * g_o[(size_t)NT * CC + i];
}

// ---------------- launch ----------------
extern "C" void kernel_launch(void* const* d_in, const int* in_sizes, int n_in,
                              void* d_out, int out_size)
{
    const float* x     = (const float*)d_in[0];
    const float* noise = (const float*)d_in[1];
    const float* Wk    = (const float*)d_in[2];
    const float* Wv    = (const float*)d_in[3];
    const float* Wq    = (const float*)d_in[4];
    const float* Wo    = (const float*)d_in[5];
    const float* Wg    = (const float*)d_in[6];
    const float* Wn    = (const float*)d_in[7];
    float* out = (float*)d_out;

    float *pk, *pv, *pq, *pat, *po, *pwkT, *pwvT, *pwqT, *pwoT;
    cudaGetSymbolAddress((void**)&pk,   g_k);
    cudaGetSymbolAddress((void**)&pv,   g_v);
    cudaGetSymbolAddress((void**)&pq,   g_q);
    cudaGetSymbolAddress((void**)&pat,  g_at);
    cudaGetSymbolAddress((void**)&po,   g_o);
    cudaGetSymbolAddress((void**)&pwkT, g_wkT);
    cudaGetSymbolAddress((void**)&pwvT, g_wvT);
    cudaGetSymbolAddress((void**)&pwqT, g_wqT);
    cudaGetSymbolAddress((void**)&pwoT, g_woT);

    cudaFuncSetAttribute(attn_flash, cudaFuncAttributeMaxDynamicSharedMemorySize, 4 * 64 * APAD * 4);

    zero_cnt<<<1, 32>>>();
    gate_kernel<<<NT, 256>>>(x, noise, Wg, Wn);

    transpose_k<<<dim3(32, 32, 1), 256>>>(Wk, pwkT);
    transpose_k<<<dim3(32, 32, 1), 256>>>(Wv, pwvT);
    transpose_k<<<dim3(32, 32, 8), 256>>>(Wq, pwqT);
    transpose_k<<<dim3(32, 32, 8), 256>>>(Wo, pwoT);

    gemm_mma<<<dim3(8, 32, 1), 256>>>(x, pwkT, pk, 0);      // k = x @ Wk
    gemm_mma<<<dim3(8, 32, 1), 256>>>(x, pwvT, pv, 0);      // v = x @ Wv
    gemm_mma<<<dim3(8, 32, 8), 256>>>(x, pwqT, pq, 1);      // q_sel = x @ Wq[sel]

    attn_flash<<<dim3(16, 16, 8), 256, 4 * 64 * APAD * 4>>>();

    gemm_mma<<<dim3(8, 32, 8), 256>>>(pat, pwoT, po, 2);    // o_sel = attn @ Wo[sel]

    combine<<<(NT * CC) / 256, 256>>>(out);
}

// round 6
// speedup vs baseline: 4.4181x; 1.9118x over previous
#include <cuda_runtime.h>
#include <math.h>
#include <cstdint>

#define TT 1024
#define CC 1024
#define EE 8
#define NT 4096   // B*T tokens
#define NR 8192   // 2 slots * NT rows

// ---------------- scratch (device globals; no allocs allowed) ----------------
__device__ float g_kv[(size_t)2 * NT * CC];       // [k | v]
__device__ float g_vT[(size_t)64 * 64 * TT];      // [b*16+h][d=64][t=1024], tf32-rounded
__device__ float g_q [(size_t)NR * CC];
__device__ float g_at[(size_t)NR * CC];           // tf32-rounded at write
__device__ float g_o [(size_t)NR * CC];
__device__ float g_xr[(size_t)NT * CC];           // tf32-rounded x
__device__ float g_w [NR];
__device__ int   g_rl[EE][NT];
__device__ int   g_cnt[EE];

__global__ void zero_cnt() { if (threadIdx.x < EE) g_cnt[threadIdx.x] = 0; }

// ---------------- PTX helpers ----------------
__device__ __forceinline__ uint32_t smem_u32(const void* p) {
    uint32_t a;
    asm("{ .reg .u64 t; cvta.to.shared.u64 t, %1; cvt.u32.u64 %0, t; }" : "=r"(a) : "l"(p));
    return a;
}
__device__ __forceinline__ uint32_t f2tf32(float x) {
    uint32_t u;
    asm("cvt.rna.tf32.f32 %0, %1;" : "=r"(u) : "f"(x));
    return u;
}
__device__ __forceinline__ float roundtf(float x) { return __uint_as_float(f2tf32(x)); }
__device__ __forceinline__ void mma_tf32(float* d, const uint32_t* a, const uint32_t* b) {
    asm volatile(
        "mma.sync.aligned.m16n8k8.row.col.f32.tf32.tf32.f32 "
        "{%0,%1,%2,%3},{%4,%5,%6,%7},{%8,%9},{%0,%1,%2,%3};"
        : "+f"(d[0]), "+f"(d[1]), "+f"(d[2]), "+f"(d[3])
        : "r"(a[0]), "r"(a[1]), "r"(a[2]), "r"(a[3]), "r"(b[0]), "r"(b[1]));
}
__device__ __forceinline__ void cp16(uint32_t dst, const void* src) {
    asm volatile("cp.async.ca.shared.global [%0], [%1], 16;" :: "r"(dst), "l"(src) : "memory");
}
#define CP_COMMIT() asm volatile("cp.async.commit_group;" ::: "memory")
#define CP_WAIT1()  asm volatile("cp.async.wait_group 1;" ::: "memory")

// ---------------- gating ----------------
__global__ __launch_bounds__(256) void gate_kernel(
    const float* __restrict__ x, const float* __restrict__ noise,
    const float* __restrict__ Wg, const float* __restrict__ Wn)
{
    int row = blockIdx.x;
    int tid = threadIdx.x;
    const float* xr = x + (size_t)row * CC;

    float accg[8], accn[8];
#pragma unroll
    for (int e = 0; e < 8; e++) { accg[e] = 0.f; accn[e] = 0.f; }
    for (int c = tid; c < CC; c += 256) {
        float xv = xr[c];
        const float* wg = Wg + c * 8;
        const float* wn = Wn + c * 8;
#pragma unroll
        for (int e = 0; e < 8; e++) { accg[e] += xv * wg[e]; accn[e] += xv * wn[e]; }
    }
    __shared__ float red[16][256];
#pragma unroll
    for (int e = 0; e < 8; e++) { red[e][tid] = accg[e]; red[8 + e][tid] = accn[e]; }
    __syncthreads();
    __shared__ float fin[16];
    if (tid < 16) {
        float s = 0.f;
        for (int i = 0; i < 256; i++) s += red[tid][i];
        fin[tid] = s;
    }
    __syncthreads();
    if (tid == 0) {
        float logit[8];
#pragma unroll
        for (int e = 0; e < 8; e++) {
            float z  = fin[8 + e];
            float sp = (z > 20.f) ? z : log1pf(expf(z));
            logit[e] = fin[e] + noise[row * 8 + e] * sp;
        }
        int i0 = 0; float v0 = logit[0];
#pragma unroll
        for (int e = 1; e < 8; e++) if (logit[e] > v0) { v0 = logit[e]; i0 = e; }
        int i1 = -1; float v1 = -INFINITY;
#pragma unroll
        for (int e = 0; e < 8; e++) if (e != i0 && logit[e] > v1) { v1 = logit[e]; i1 = e; }
        float p1 = 1.f / (1.f + expf(v0 - v1));
        float p0 = 1.f - p1;
        g_w[row]      = p0;
        g_w[NT + row] = p1;
        int pos0 = atomicAdd(&g_cnt[i0], 1); g_rl[i0][pos0] = row;
        int pos1 = atomicAdd(&g_cnt[i1], 1); g_rl[i1][pos1] = NT + row;
    }
}

// ---------------- round x to tf32 ----------------
__global__ void round_x(const float* __restrict__ x, float* __restrict__ xr)
{
    int i = blockIdx.x * 256 + threadIdx.x;          // over NT*CC/4 float4
    float4 v = ((const float4*)x)[i];
    v.x = roundtf(v.x); v.y = roundtf(v.y); v.z = roundtf(v.z); v.w = roundtf(v.w);
    ((float4*)xr)[i] = v;
}

// ---------------- V transpose per (b,h): [t][d] -> [d][t], tf32-rounded ----------------
__global__ __launch_bounds__(256) void transpose_v()
{
    __shared__ float tile[32][33];
    int bh = blockIdx.z;
    int b = bh >> 4, h = bh & 15;
    int t0 = blockIdx.x * 32, d0 = blockIdx.y * 32;
    int tx = threadIdx.x & 31, ty = threadIdx.x >> 5;
    const float* src = g_kv + (size_t)NT * CC;
#pragma unroll
    for (int r = 0; r < 4; r++) {
        int tt = t0 + ty + r * 8;
        tile[ty + r * 8][tx] = src[(size_t)(b * TT + tt) * CC + h * 64 + d0 + tx];
    }
    __syncthreads();
#pragma unroll
    for (int r = 0; r < 4; r++) {
        int dd = d0 + ty + r * 8;
        g_vT[((size_t)bh * 64 + dd) * TT + t0 + tx] = roundtf(tile[tx][ty + r * 8]);
    }
}

// ---------------- tf32 mma GEMM, cp.async 3-stage, 4 warps x (64x64) ----------------
// C[rows,1024] = A[rows,1024] @ W_e  (W stored [e][k][n] row-major, no transpose)
// mode 3: dense k/v fused (z selects W/W2 and output half). mode 1: gather token
// rows (src = rl & 4095). mode 2: gather direct rows (src = rl).
#define AST 36
#define BST 136
#define GS_A (128 * AST)
#define GS_B (32 * BST)
__global__ __launch_bounds__(128) void gemm_mma(
    const float* __restrict__ A, const float* __restrict__ W,
    const float* __restrict__ W2, float* __restrict__ C, int mode)
{
    extern __shared__ float smg[];
    float* As = smg;                 // [3][128][36]
    float* Bs = smg + 3 * GS_A;      // [3][32][136]
    __shared__ int s_src[128];
    __shared__ int s_dst[128];

    int tid = threadIdx.x, lane = tid & 31, wid = tid >> 5;
    int z = blockIdx.z, row0 = blockIdx.y * 128, n0 = blockIdx.x * 128;

    const float* Wb;
    float* Cout = C;
    int cnt = NT;
    if (mode == 3) { Wb = z ? W2 : W; Cout = C + (size_t)z * NT * CC; }
    else {
        Wb = W + (size_t)z * CC * CC;
        cnt = g_cnt[z];
        if (row0 >= cnt) return;
    }
    {
        int gr = row0 + tid;
        if (mode == 3) { s_src[tid] = gr; s_dst[tid] = gr; }
        else if (gr < cnt) {
            int r = g_rl[z][gr];
            s_src[tid] = (mode == 1) ? (r & (NT - 1)) : r;
            s_dst[tid] = r;
        } else { s_src[tid] = 0; s_dst[tid] = -1; }
    }
    __syncthreads();

    const float* aptr[8];
    uint32_t adst[8];
    uint32_t sbA = smem_u32(As);
    uint32_t sbB = smem_u32(Bs);
#pragma unroll
    for (int i = 0; i < 8; i++) {
        int r = (tid >> 3) + 16 * i;
        aptr[i] = A + (size_t)s_src[r] * CC + (tid & 7) * 4;
        adst[i] = sbA + (uint32_t)(r * AST + (tid & 7) * 4) * 4;
    }
    const float* bptr = Wb + (size_t)(tid >> 5) * CC + n0 + lane * 4;
    uint32_t bdst0 = sbB + (uint32_t)((tid >> 5) * BST + lane * 4) * 4;

    auto issue = [&](int c, int stg) {
        int k0 = c * 32;
        uint32_t ao = (uint32_t)stg * GS_A * 4;
        uint32_t bo = (uint32_t)stg * GS_B * 4;
#pragma unroll
        for (int i = 0; i < 8; i++) cp16(adst[i] + ao, aptr[i] + k0);
#pragma unroll
        for (int i = 0; i < 8; i++)
            cp16(bdst0 + bo + (uint32_t)i * 4 * BST * 4, bptr + (size_t)(k0 + 4 * i) * CC);
        CP_COMMIT();
    };

    float acc[4][8][4];
#pragma unroll
    for (int mt = 0; mt < 4; mt++)
#pragma unroll
        for (int nt = 0; nt < 8; nt++)
#pragma unroll
            for (int q = 0; q < 4; q++) acc[mt][nt][q] = 0.f;

    int wm = (wid >> 1) * 64;
    int wn = (wid & 1) * 64;

    issue(0, 0); issue(1, 1);
#pragma unroll 1
    for (int c = 0; c < 32; c++) {
        int stg = c % 3;
        CP_WAIT1();
        __syncthreads();
        if (c + 2 < 32) issue(c + 2, (c + 2) % 3);
        const float* Ab = As + stg * GS_A;
        const float* Bb = Bs + stg * GS_B;
#pragma unroll
        for (int k8 = 0; k8 < 4; k8++) {
            int kc = k8 * 8 + (lane & 3);
            uint32_t af[4][4];
#pragma unroll
            for (int mt = 0; mt < 4; mt++) {
                int r = wm + mt * 16 + (lane >> 2);
                af[mt][0] = __float_as_uint(Ab[r * AST + kc]);
                af[mt][1] = __float_as_uint(Ab[(r + 8) * AST + kc]);
                af[mt][2] = __float_as_uint(Ab[r * AST + kc + 4]);
                af[mt][3] = __float_as_uint(Ab[(r + 8) * AST + kc + 4]);
            }
#pragma unroll
            for (int nt = 0; nt < 8; nt++) {
                int n = wn + nt * 8 + (lane >> 2);
                uint32_t bf[2];
                bf[0] = f2tf32(Bb[kc * BST + n]);
                bf[1] = f2tf32(Bb[(kc + 4) * BST + n]);
#pragma unroll
                for (int mt = 0; mt < 4; mt++)
                    mma_tf32(acc[mt][nt], af[mt], bf);
            }
        }
    }

    int r0 = wm + (lane >> 2);
    int cb = n0 + wn + (lane & 3) * 2;
#pragma unroll
    for (int mt = 0; mt < 4; mt++) {
        int dA = s_dst[r0 + mt * 16];
        int dB = s_dst[r0 + mt * 16 + 8];
#pragma unroll
        for (int nt = 0; nt < 8; nt++) {
            int gc = cb + nt * 8;
            if (dA >= 0)
                *(float2*)(Cout + (size_t)dA * CC + gc) = make_float2(acc[mt][nt][0], acc[mt][nt][1]);
            if (dB >= 0)
                *(float2*)(Cout + (size_t)dB * CC + gc) = make_float2(acc[mt][nt][2], acc[mt][nt][3]);
        }
    }
}

// ---------------- flash attention, tf32 mma: 128-row Q tiles ----------------
// grid (8 qtiles, 16 heads, 8 = slot*4+b), 128 threads = 4 warps x (32 rows, 64 cols)
#define KP 68
__global__ __launch_bounds__(128) void attn_mma()
{
    extern __shared__ float sm[];
    float* Qs = sm;                    // [128][KP] i-major, d contiguous (tf32)
    float* Ks = sm + 128 * KP;         // [64][KP]  j-major, d contiguous (tf32)
    float* Vt = Ks + 64 * KP;          // [64][KP]  d-major, j contiguous (tf32)
    float* Ps = Vt + 64 * KP;          // [128][KP] i-major, j contiguous (tf32)

    int tid = threadIdx.x, lane = tid & 31, wid = tid >> 5;
    int qt = 7 - (int)blockIdx.x;      // longest blocks first
    int h  = blockIdx.y;
    int zb = blockIdx.z;
    int s = zb >> 2, b = zb & 3;
    int rbase = s * NT + b * TT;
    const float* qsrc  = g_q + (size_t)(rbase + qt * 128) * CC + h * 64;
    const float* ksrc  = g_kv + (size_t)(b * TT) * CC + h * 64;
    const float* vtsrc = g_vT + (size_t)(b * 16 + h) * 64 * TT;

    // stage Q (tf32)
#pragma unroll
    for (int it = 0; it < 16; it++) {
        int idx = tid + it * 128;
        int r = idx >> 4, d0 = (idx & 15) * 4;
        float4 v = *(const float4*)(qsrc + (size_t)r * CC + d0);
        v.x = roundtf(v.x); v.y = roundtf(v.y); v.z = roundtf(v.z); v.w = roundtf(v.w);
        *(float4*)(Qs + r * KP + d0) = v;
    }

    float Oa[2][8][4];
    float mrow[4], lrow[4];
#pragma unroll
    for (int mt = 0; mt < 2; mt++)
#pragma unroll
        for (int nt = 0; nt < 8; nt++)
#pragma unroll
            for (int q = 0; q < 4; q++) Oa[mt][nt][q] = 0.f;
#pragma unroll
    for (int i = 0; i < 4; i++) { mrow[i] = -1e30f; lrow[i] = 0.f; }

    int ktmax = 2 * qt + 1;
#pragma unroll 1
    for (int kt = 0; kt <= ktmax; kt++) {
        // stage K (cvt) and V tile (pre-rounded)
        const float* ks2 = ksrc + (size_t)(kt * 64) * CC;
#pragma unroll
        for (int it = 0; it < 8; it++) {
            int idx = tid + it * 128;
            int j = idx >> 4, d0 = (idx & 15) * 4;
            float4 kv = *(const float4*)(ks2 + (size_t)j * CC + d0);
            kv.x = roundtf(kv.x); kv.y = roundtf(kv.y); kv.z = roundtf(kv.z); kv.w = roundtf(kv.w);
            *(float4*)(Ks + j * KP + d0) = kv;
            int d = idx >> 4, j0 = (idx & 15) * 4;
            float4 vv = *(const float4*)(vtsrc + (size_t)d * TT + kt * 64 + j0);
            *(float4*)(Vt + d * KP + j0) = vv;
        }
        __syncthreads();

        // S = Q @ K^T
        float sa[2][8][4];
#pragma unroll
        for (int mt = 0; mt < 2; mt++)
#pragma unroll
            for (int nt = 0; nt < 8; nt++)
#pragma unroll
                for (int q = 0; q < 4; q++) sa[mt][nt][q] = 0.f;
#pragma unroll
        for (int k8 = 0; k8 < 8; k8++) {
            int kc = k8 * 8 + (lane & 3);
            uint32_t af[2][4];
#pragma unroll
            for (int mt = 0; mt < 2; mt++) {
                int r = wid * 32 + mt * 16 + (lane >> 2);
                af[mt][0] = __float_as_uint(Qs[r * KP + kc]);
                af[mt][1] = __float_as_uint(Qs[(r + 8) * KP + kc]);
                af[mt][2] = __float_as_uint(Qs[r * KP + kc + 4]);
                af[mt][3] = __float_as_uint(Qs[(r + 8) * KP + kc + 4]);
            }
#pragma unroll
            for (int nt = 0; nt < 8; nt++) {
                int n = nt * 8 + (lane >> 2);
                uint32_t bf[2];
                bf[0] = __float_as_uint(Ks[n * KP + kc]);
                bf[1] = __float_as_uint(Ks[n * KP + kc + 4]);
#pragma unroll
                for (int mt = 0; mt < 2; mt++)
                    mma_tf32(sa[mt][nt], af[mt], bf);
            }
        }

        // online softmax + P store
        bool domask = (kt >= 2 * qt);
#pragma unroll
        for (int mt = 0; mt < 2; mt++) {
            int rl = wid * 32 + mt * 16 + (lane >> 2);
#pragma unroll
            for (int half = 0; half < 2; half++) {
                int mi = mt * 2 + half;
                int ig = qt * 128 + rl + half * 8;
                float v[16];
#pragma unroll
                for (int nt = 0; nt < 8; nt++) {
                    float s0 = sa[mt][nt][half * 2 + 0] * 0.125f;
                    float s1 = sa[mt][nt][half * 2 + 1] * 0.125f;
                    if (domask) {
                        int jg = kt * 64 + nt * 8 + 2 * (lane & 3);
                        if (jg > ig)     s0 = -1e30f;
                        if (jg + 1 > ig) s1 = -1e30f;
                    }
                    v[nt * 2] = s0; v[nt * 2 + 1] = s1;
                }
                float rm = v[0];
#pragma unroll
                for (int j = 1; j < 16; j++) rm = fmaxf(rm, v[j]);
                rm = fmaxf(rm, __shfl_xor_sync(0xFFFFFFFFu, rm, 1));
                rm = fmaxf(rm, __shfl_xor_sync(0xFFFFFFFFu, rm, 2));
                float mn = fmaxf(mrow[mi], rm);
                float alpha = __expf(mrow[mi] - mn);
                float rs = 0.f;
#pragma unroll
                for (int j = 0; j < 16; j++) { float p = __expf(v[j] - mn); v[j] = p; rs += p; }
                rs += __shfl_xor_sync(0xFFFFFFFFu, rs, 1);
                rs += __shfl_xor_sync(0xFFFFFFFFu, rs, 2);
                mrow[mi] = mn;
                lrow[mi] = lrow[mi] * alpha + rs;
#pragma unroll
                for (int nt = 0; nt < 8; nt++) {
                    Oa[mt][nt][half * 2 + 0] *= alpha;
                    Oa[mt][nt][half * 2 + 1] *= alpha;
                }
                int prow = rl + half * 8;
#pragma unroll
                for (int nt = 0; nt < 8; nt++) {
                    Ps[prow * KP + nt * 8 + 2 * (lane & 3)]     = roundtf(v[nt * 2]);
                    Ps[prow * KP + nt * 8 + 2 * (lane & 3) + 1] = roundtf(v[nt * 2 + 1]);
                }
            }
        }
        __syncwarp();

        // O += P @ V  (A = own 32-row band of Ps)
#pragma unroll
        for (int k8 = 0; k8 < 8; k8++) {
            int kc = k8 * 8 + (lane & 3);
            uint32_t af[2][4];
#pragma unroll
            for (int mt = 0; mt < 2; mt++) {
                int r = wid * 32 + mt * 16 + (lane >> 2);
                af[mt][0] = __float_as_uint(Ps[r * KP + kc]);
                af[mt][1] = __float_as_uint(Ps[(r + 8) * KP + kc]);
                af[mt][2] = __float_as_uint(Ps[r * KP + kc + 4]);
                af[mt][3] = __float_as_uint(Ps[(r + 8) * KP + kc + 4]);
            }
#pragma unroll
            for (int nt = 0; nt < 8; nt++) {
                int n = nt * 8 + (lane >> 2);
                uint32_t bf[2];
                bf[0] = __float_as_uint(Vt[n * KP + kc]);
                bf[1] = __float_as_uint(Vt[n * KP + kc + 4]);
#pragma unroll
                for (int mt = 0; mt < 2; mt++)
                    mma_tf32(Oa[mt][nt], af[mt], bf);
            }
        }
        __syncthreads();
    }

    // write O (tf32-rounded: pre-rounds the o-GEMM's A operand)
#pragma unroll
    for (int mt = 0; mt < 2; mt++) {
        int rl = wid * 32 + mt * 16 + (lane >> 2);
#pragma unroll
        for (int half = 0; half < 2; half++) {
            int mi = mt * 2 + half;
            float inv = 1.f / lrow[mi];
            float* orow = g_at + (size_t)(rbase + qt * 128 + rl + half * 8) * CC + h * 64;
#pragma unroll
            for (int nt = 0; nt < 8; nt++) {
                float c0 = roundtf(Oa[mt][nt][half * 2 + 0] * inv);
                float c1 = roundtf(Oa[mt][nt][half * 2 + 1] * inv);
                *(float2*)(orow + nt * 8 + 2 * (lane & 3)) = make_float2(c0, c1);
            }
        }
    }
}

// ---------------- final combine ----------------
__global__ void combine(float* __restrict__ out)
{
    int i = blockIdx.x * 256 + threadIdx.x;
    int token = i >> 10;
    out[i] = g_w[token] * g_o[i] + g_w[NT + token] * g_o[(size_t)NT * CC + i];
}

// ---------------- launch ----------------
extern "C" void kernel_launch(void* const* d_in, const int* in_sizes, int n_in,
                              void* d_out, int out_size)
{
    const float* x     = (const float*)d_in[0];
    const float* noise = (const float*)d_in[1];
    const float* Wk    = (const float*)d_in[2];
    const float* Wv    = (const float*)d_in[3];
    const float* Wq    = (const float*)d_in[4];
    const float* Wo    = (const float*)d_in[5];
    const float* Wg    = (const float*)d_in[6];
    const float* Wn    = (const float*)d_in[7];
    float* out = (float*)d_out;

    float *pkv, *pq, *pat, *po, *pxr;
    cudaGetSymbolAddress((void**)&pkv, g_kv);
    cudaGetSymbolAddress((void**)&pq,  g_q);
    cudaGetSymbolAddress((void**)&pat, g_at);
    cudaGetSymbolAddress((void**)&po,  g_o);
    cudaGetSymbolAddress((void**)&pxr, g_xr);

    const int gemm_smem = (3 * GS_A + 3 * GS_B) * 4;      // 107520
    const int attn_smem = 384 * KP * 4;                   // 104448
    cudaFuncSetAttribute(gemm_mma, cudaFuncAttributeMaxDynamicSharedMemorySize, gemm_smem);
    cudaFuncSetAttribute(attn_mma, cudaFuncAttributeMaxDynamicSharedMemorySize, attn_smem);

    zero_cnt<<<1, 32>>>();
    gate_kernel<<<NT, 256>>>(x, noise, Wg, Wn);
    round_x<<<(NT * CC / 4) / 256, 256>>>(x, pxr);

    gemm_mma<<<dim3(8, 32, 2), 128, gemm_smem>>>(pxr, Wk, Wv, pkv, 3);   // k|v
    gemm_mma<<<dim3(8, 32, 8), 128, gemm_smem>>>(pxr, Wq, Wq, pq, 1);    // q_sel

    transpose_v<<<dim3(32, 2, 64), 256>>>();

    attn_mma<<<dim3(8, 16, 8), 128, attn_smem>>>();

    gemm_mma<<<dim3(8, 32, 8), 128, gemm_smem>>>(pat, Wo, Wo, po, 2);    // o_sel

    combine<<<(NT * CC) / 256, 256>>>(out);
}